// round 3
// baseline (speedup 1.0000x reference)
#include <cuda_runtime.h>
#include <cuda_bf16.h>
#include <cstdint>

#define BB 64
#define SS 512
#define DD 1024
#define HH 1024
#define TT 9
#define NC 16        // time chunks per batch
#define CL 32        // steps per chunk
#define NCHAIN (BB*NC)       // 1024 chains
#define CPW 3                // chains per warp
#define NWARP ((NCHAIN + CPW - 1) / CPW)   // 342

// packed f32x2 helpers (Blackwell packed fp32 — PTX only, ptxas won't fuse)
#define FMA2(d,a,b,c) asm("fma.rn.f32x2 %0, %1, %2, %3;" : "=l"(d) : "l"(a), "l"(b), "l"(c))
#define ADD2(d,a,b)   asm("add.rn.f32x2 %0, %1, %2;"     : "=l"(d) : "l"(a), "l"(b))
#define PACK2(d,lo,hi) asm("mov.b64 %0, {%1, %2};" : "=l"(d) : "r"(__float_as_uint(lo)), "r"(__float_as_uint(hi)))

// Scratch (device globals; no allocation allowed)
__device__ float g_WeffT[TT * DD];     // SoA: [t][d]
__device__ float g_beff[TT];
__device__ float g_P[NCHAIN * 81];     // per-chunk 9x9 log-domain composite
__device__ float g_res[BB];            // per-batch (logz - score)

// ---------------------------------------------------------------------------
// Kernel 1: WeffT[t][d] = sum_h W1[d,h]*W2[h,t];  beff = b1@W2 + b2
// ---------------------------------------------------------------------------
__global__ __launch_bounds__(256) void weff_kernel(
    const float* __restrict__ W1, const float* __restrict__ b1,
    const float* __restrict__ W2, const float* __restrict__ b2)
{
    __shared__ float sW2[HH * TT];     // 36 KB
    int tid = threadIdx.x;
    for (int i = tid; i < HH * TT; i += 256) sW2[i] = W2[i];
    __syncthreads();

    int w = tid >> 5, l = tid & 31;
    bool isb = (blockIdx.x == DD / 8);
    if (isb && w > 0) return;
    int d = blockIdx.x * 8 + w;
    const float* src = isb ? b1 : (W1 + (size_t)d * HH);

    float acc[TT];
#pragma unroll
    for (int t = 0; t < TT; t++) acc[t] = 0.f;
    for (int h = l; h < HH; h += 32) {
        float a = src[h];
        const float* r = sW2 + h * TT;
#pragma unroll
        for (int t = 0; t < TT; t++) acc[t] = fmaf(a, r[t], acc[t]);
    }
#pragma unroll
    for (int t = 0; t < TT; t++)
#pragma unroll
        for (int o = 16; o; o >>= 1)
            acc[t] += __shfl_xor_sync(0xffffffffu, acc[t], o);

    if (l == 0) {
        if (isb) {
#pragma unroll
            for (int t = 0; t < TT; t++) g_beff[t] = acc[t] + b2[t];
        } else {
#pragma unroll
            for (int t = 0; t < TT; t++) g_WeffT[t * DD + d] = acc[t];
        }
    }
}

// ---------------------------------------------------------------------------
// Kernel 2: logits = input @ Weff + beff.  512 blocks x 256 thr.
// Warp handles 8 rows; lane owns d = k*32+lane (coalesced scalar LDG).
// WeffT in smem SoA (stride-1 LDS). Packed f32x2 FMA: 2 rows per instr.
// ---------------------------------------------------------------------------
__global__ __launch_bounds__(256) void gemv_kernel(
    const float* __restrict__ input, float* __restrict__ logits)
{
    __shared__ float sWt[TT * DD];     // 36 KB, [t][d]
    int tid = threadIdx.x;
    for (int i = tid; i < TT * DD; i += 256) sWt[i] = g_WeffT[i];
    __syncthreads();

    int w = tid >> 5, lane = tid & 31;
    int rowbase = (blockIdx.x * 8 + w) * 8;
    const float* ip = input + (size_t)rowbase * DD;

    unsigned long long acc2[4][TT];    // pair p = rows (2p, 2p+1) in (lo,hi)
#pragma unroll
    for (int p = 0; p < 4; p++)
#pragma unroll
        for (int t = 0; t < TT; t++) acc2[p][t] = 0ull;

    for (int k = 0; k < 32; k++) {
        int d = k * 32 + lane;
        unsigned long long wp[TT];
#pragma unroll
        for (int t = 0; t < TT; t++) {
            float wv = sWt[t * DD + d];
            PACK2(wp[t], wv, wv);
        }
        float x[8];
#pragma unroll
        for (int r = 0; r < 8; r++) x[r] = ip[(size_t)r * DD + d];
        unsigned long long xp[4];
#pragma unroll
        for (int p = 0; p < 4; p++) PACK2(xp[p], x[2 * p], x[2 * p + 1]);
#pragma unroll
        for (int p = 0; p < 4; p++)
#pragma unroll
            for (int t = 0; t < TT; t++)
                FMA2(acc2[p][t], xp[p], wp[t], acc2[p][t]);
    }

    // packed butterfly reduce across lanes
#pragma unroll
    for (int p = 0; p < 4; p++)
#pragma unroll
        for (int t = 0; t < TT; t++)
#pragma unroll
            for (int o = 16; o; o >>= 1) {
                unsigned long long other = __shfl_xor_sync(0xffffffffu, acc2[p][t], o);
                ADD2(acc2[p][t], acc2[p][t], other);
            }

    if (lane < 8) {
        int p = lane >> 1, half = lane & 1;
        float* o = logits + (size_t)(rowbase + lane) * TT;
#pragma unroll
        for (int t = 0; t < TT; t++) {
            unsigned lo, hi;
            asm("mov.b64 {%0, %1}, %2;" : "=r"(lo), "=r"(hi) : "l"(acc2[p][t]));
            float v = __uint_as_float(half ? hi : lo);
            o[t] = v + g_beff[t];
        }
    }
}

// ---------------------------------------------------------------------------
// Kernel 3: chunk composites. 3 chains per warp (lanes 0..26; 9-lane groups).
// Linear-domain chain with diagonal-entry renorm every 8 steps.
// grid 43 blocks x 256 thr (warps 342..343 idle).
// ---------------------------------------------------------------------------
__global__ __launch_bounds__(256) void crf_chunk_kernel(
    const float* __restrict__ logits, const int* __restrict__ mask,
    const float* __restrict__ trans)
{
    __shared__ float s_em[8][CPW][CL * TT];
    __shared__ int   s_mk[8][CPW][CL];

    int w = threadIdx.x >> 5, l = threadIdx.x & 31;
    int wg = blockIdx.x * 8 + w;
    if (wg >= NWARP) return;

    // cooperative load of this warp's 3 chains
    for (int i = l; i < CPW * CL * TT; i += 32) {
        int ch = i / (CL * TT), off = i % (CL * TT);
        int n = wg * CPW + ch;
        float v = 0.f;
        if (n < NCHAIN) {
            int b = n >> 4, c = n & 15;
            int t = 1 + c * CL + off / TT;
            if (t < SS) v = logits[((size_t)b * SS + t) * TT + off % TT];
        }
        s_em[w][ch][off] = v;
    }
    for (int i = l; i < CPW * CL; i += 32) {
        int ch = i / CL, s = i % CL;
        int n = wg * CPW + ch;
        int mv = 0;
        if (n < NCHAIN) {
            int b = n >> 4, c = n & 15;
            int t = 1 + c * CL + s;
            if (t < SS) mv = mask[(size_t)b * SS + t];
        }
        s_mk[w][ch][s] = mv;
    }
    __syncwarp();

    int g = (l < 27) ? (l / TT) : 2;       // group (chain within warp)
    int j = l - g * TT;                    // column 0..8 (junk for l>=27)
    bool act = (l < 27) && (j < TT) && (wg * CPW + g < NCHAIN);
    int gbase = g * TT;

    float E[TT];
#pragma unroll
    for (int k = 0; k < TT; k++)
        E[k] = act ? __expf(trans[k * TT + j]) : 0.f;

    float R[TT], Ms[TT];
#pragma unroll
    for (int i = 0; i < TT; i++) { R[i] = (act && i == j) ? 1.f : 0.f; Ms[i] = 0.f; }

    const float* em = s_em[w][g];
    const int*   mk = s_mk[w][g];

    for (int s = 0; s < CL; s++) {
        int m = mk[s];
        float eem = __expf(act ? em[s * TT + j] : 0.f);
#pragma unroll
        for (int i = 0; i < TT; i++) {
            float v = R[i];
            float sum = 0.f;
#pragma unroll
            for (int k = 0; k < TT; k++)
                sum = fmaf(__shfl_sync(0xffffffffu, v, gbase + k), E[k], sum);
            R[i] = (m != 0) ? sum * eem : R[i];
        }
        if ((s & 7) == 7) {
#pragma unroll
            for (int i = 0; i < TT; i++) {
                float sc = __shfl_sync(0xffffffffu, R[i], gbase + i);  // diagonal entry > 0
                float r = __fdividef(1.f, sc);
                R[i] *= r;
                Ms[i] += __logf(sc);
            }
        }
    }
    if (act) {
        int n = wg * CPW + g;
        float* Pp = g_P + (size_t)n * 81;
#pragma unroll
        for (int i = 0; i < TT; i++) Pp[i * TT + j] = Ms[i] + __logf(R[i]);
    }
}

// ---------------------------------------------------------------------------
// Kernel 4: per-batch combine. Block of 256 threads per batch.
// Tree of 9x9 log-semiring products (4 levels), + numerator + logz.
// ---------------------------------------------------------------------------
__global__ __launch_bounds__(256) void crf_combine_kernel(
    const float* __restrict__ logits, const int* __restrict__ labels,
    const int* __restrict__ mask, const float* __restrict__ start,
    const float* __restrict__ endt, const float* __restrict__ trans)
{
    __shared__ float sP[NC * 108];     // matrix c at c*108, entry [i][j] at i*12+j
    __shared__ int   s_mk[SS];
    __shared__ int   s_tg[SS];
    __shared__ float s_red[256];
    __shared__ int   s_ridx[256];
    __shared__ float s_alpha[TT];
    __shared__ float s_score;

    int b = blockIdx.x, tid = threadIdx.x;

    // load composites + mask + labels
    const float* Pb = g_P + (size_t)b * NC * 81;
    for (int i = tid; i < NC * 81; i += 256) {
        int c = i / 81, r = i % 81;
        sP[c * 108 + (r / TT) * 12 + r % TT] = Pb[i];
    }
    for (int i = tid; i < SS; i += 256) {
        s_mk[i] = mask[(size_t)b * SS + i];
        s_tg[i] = labels[(size_t)b * SS + i];
    }
    __syncthreads();

    // ---- numerator partial + last-masked-index (each thread: t, t+256) ----
    float contrib = 0.f;
    int ridx = 0;
#pragma unroll
    for (int h = 0; h < 2; h++) {
        int t = tid + h * 256;
        if (t == 0) {
            contrib += start[s_tg[0]] + logits[(size_t)b * SS * TT + s_tg[0]];
        } else if (s_mk[t] > 0) {
            int tp = t - 1;
            while (tp > 0 && s_mk[tp] == 0) tp--;
            contrib += trans[s_tg[tp] * TT + s_tg[t]]
                     + logits[((size_t)b * SS + t) * TT + s_tg[t]];
            ridx = max(ridx, t);
        }
    }
    s_red[tid] = contrib;
    s_ridx[tid] = ridx;
    __syncthreads();
#pragma unroll
    for (int o = 128; o; o >>= 1) {
        if (tid < o) {
            s_red[tid] += s_red[tid + o];
            s_ridx[tid] = max(s_ridx[tid], s_ridx[tid + o]);
        }
        __syncthreads();
    }
    if (tid == 0) s_score = s_red[0] + endt[s_tg[s_ridx[0]]];

    // ---- tree combine: 4 levels; level L: (8>>L) warps, stride 1<<L ----
    int w = tid >> 5, lane = tid & 31;
#pragma unroll
    for (int L = 0; L < 4; L++) {
        __syncthreads();
        int nprod = 8 >> L, stride = 1 << L;
        if (w < nprod && lane < TT) {
            int a = (w * 2) * stride, bb2 = a + stride;
            const float* A = sP + a * 108;
            const float* Bc = sP + bb2 * 108;
            float Bcol[TT];
#pragma unroll
            for (int k = 0; k < TT; k++) Bcol[k] = Bc[k * 12 + lane];
            float C[TT];
#pragma unroll
            for (int i = 0; i < TT; i++) {
                float vmax = -1e30f;
                float vv[TT];
#pragma unroll
                for (int k = 0; k < TT; k++) {
                    vv[k] = A[i * 12 + k] + Bcol[k];
                    vmax = fmaxf(vmax, vv[k]);
                }
                float ssum = 0.f;
#pragma unroll
                for (int k = 0; k < TT; k++) ssum += __expf(vv[k] - vmax);
                C[i] = vmax + __logf(ssum);
            }
            float* Cs = sP + a * 108;
#pragma unroll
            for (int i = 0; i < TT; i++) Cs[i * 12 + lane] = C[i];
        }
    }
    __syncthreads();

    // ---- final: alpha0 (x) P, logz, result ----
    if (w == 0) {
        if (lane < TT)
            s_alpha[lane] = start[lane] + logits[(size_t)b * SS * TT + lane];
        __syncwarp();
        float v = -1e30f;
        if (lane < TT) {
            float vmax = -1e30f, vv[TT];
#pragma unroll
            for (int i = 0; i < TT; i++) {
                vv[i] = s_alpha[i] + sP[i * 12 + lane];
                vmax = fmaxf(vmax, vv[i]);
            }
            float ssum = 0.f;
#pragma unroll
            for (int i = 0; i < TT; i++) ssum += __expf(vv[i] - vmax);
            v = vmax + __logf(ssum) + endt[lane];
        }
        float Mx = v;
#pragma unroll
        for (int o = 16; o; o >>= 1) Mx = fmaxf(Mx, __shfl_xor_sync(0xffffffffu, Mx, o));
        float e = __expf(v - Mx);
#pragma unroll
        for (int o = 16; o; o >>= 1) e += __shfl_xor_sync(0xffffffffu, e, o);
        if (lane == 0) g_res[b] = (Mx + __logf(e)) - s_score;
    }
}

// ---------------------------------------------------------------------------
// Kernel 5: loss = mean(res), fixed-order reduce
// ---------------------------------------------------------------------------
__global__ __launch_bounds__(64) void final_kernel(float* __restrict__ out)
{
    __shared__ float sv[BB];
    int t = threadIdx.x;
    sv[t] = g_res[t];
    __syncthreads();
#pragma unroll
    for (int o = 32; o; o >>= 1) {
        if (t < o) sv[t] += sv[t + o];
        __syncthreads();
    }
    if (t == 0) out[0] = sv[0] * (1.0f / 64.0f);
}

// ---------------------------------------------------------------------------
extern "C" void kernel_launch(void* const* d_in, const int* in_sizes, int n_in,
                              void* d_out, int out_size)
{
    const float* input  = (const float*)d_in[0];
    const int*   labels = (const int*)  d_in[1];
    const int*   mask   = (const int*)  d_in[2];
    const float* W1     = (const float*)d_in[3];
    const float* b1     = (const float*)d_in[4];
    const float* W2     = (const float*)d_in[5];
    const float* b2     = (const float*)d_in[6];
    const float* start  = (const float*)d_in[7];
    const float* endt   = (const float*)d_in[8];
    const float* trans  = (const float*)d_in[9];

    float* out    = (float*)d_out;
    float* logits = out + 1;   // output layout: [loss, logits(B,S,T)]

    weff_kernel<<<DD / 8 + 1, 256>>>(W1, b1, W2, b2);
    gemv_kernel<<<512, 256>>>(input, logits);
    crf_chunk_kernel<<<(NWARP + 7) / 8, 256>>>(logits, mask, trans);
    crf_combine_kernel<<<BB, 256>>>(logits, labels, mask, start, endt, trans);
    final_kernel<<<1, BB>>>(out);
}

// round 4
// speedup vs baseline: 1.6665x; 1.6665x over previous
#include <cuda_runtime.h>
#include <cuda_bf16.h>
#include <cstdint>

#define BB 64
#define SS 512
#define DD 1024
#define HH 1024
#define TT 9
#define NC 16        // time chunks per batch
#define CL 32        // steps per chunk

// Scratch (device globals; no allocation allowed)
__device__ float g_WeffT[TT * DD];     // SoA: [t][d]
__device__ float g_beff[TT];
__device__ float g_P[BB * NC * 81];    // per-chunk 9x9 log-domain composite
__device__ float g_res[BB];            // per-batch (logz - score)

// ---------------------------------------------------------------------------
// Kernel 1: WeffT[t][d] = sum_h W1[d,h]*W2[h,t];  beff = b1@W2 + b2
// ---------------------------------------------------------------------------
__global__ __launch_bounds__(256) void weff_kernel(
    const float* __restrict__ W1, const float* __restrict__ b1,
    const float* __restrict__ W2, const float* __restrict__ b2)
{
    __shared__ float sW2[HH * TT];     // 36 KB
    int tid = threadIdx.x;
    for (int i = tid; i < HH * TT; i += 256) sW2[i] = W2[i];
    __syncthreads();

    int w = tid >> 5, l = tid & 31;
    bool isb = (blockIdx.x == DD / 8);
    if (isb && w > 0) return;
    int d = blockIdx.x * 8 + w;
    const float* src = isb ? b1 : (W1 + (size_t)d * HH);

    float acc[TT];
#pragma unroll
    for (int t = 0; t < TT; t++) acc[t] = 0.f;
    for (int h = l; h < HH; h += 32) {
        float a = src[h];
        const float* r = sW2 + h * TT;
#pragma unroll
        for (int t = 0; t < TT; t++) acc[t] = fmaf(a, r[t], acc[t]);
    }
#pragma unroll
    for (int t = 0; t < TT; t++)
#pragma unroll
        for (int o = 16; o; o >>= 1)
            acc[t] += __shfl_xor_sync(0xffffffffu, acc[t], o);

    if (l == 0) {
        if (isb) {
#pragma unroll
            for (int t = 0; t < TT; t++) g_beff[t] = acc[t] + b2[t];
        } else {
#pragma unroll
            for (int t = 0; t < TT; t++) g_WeffT[t * DD + d] = acc[t];
        }
    }
}

// ---------------------------------------------------------------------------
// Kernel 2: logits = input @ Weff + beff.
// 1024 blocks x 256 thr. Warp owns 4 rows; lane owns d = k*32+lane, so every
// global load is one 128B line per warp (fully coalesced). Weff SoA in smem
// (stride-1 LDS). Plain FFMA, ~60 regs. DRAM-bound (~22us floor).
// ---------------------------------------------------------------------------
__global__ __launch_bounds__(256) void gemv_kernel(
    const float* __restrict__ input, float* __restrict__ logits)
{
    __shared__ float sWt[TT * DD];     // 36 KB, [t][d]
    int tid = threadIdx.x;
    for (int i = tid; i < TT * DD; i += 256) sWt[i] = g_WeffT[i];
    __syncthreads();

    int w = tid >> 5, lane = tid & 31;
    int rowbase = (blockIdx.x * 8 + w) * 4;
    const float* ip = input + (size_t)rowbase * DD;

    float acc[4][TT];
#pragma unroll
    for (int r = 0; r < 4; r++)
#pragma unroll
        for (int t = 0; t < TT; t++) acc[r][t] = 0.f;

#pragma unroll 2
    for (int k = 0; k < 32; k++) {
        int d = (k << 5) + lane;
        float x[4];
#pragma unroll
        for (int r = 0; r < 4; r++) x[r] = ip[(size_t)r * DD + d];  // 4 coalesced LDG
        float wv[TT];
#pragma unroll
        for (int t = 0; t < TT; t++) wv[t] = sWt[t * DD + d];       // stride-1 LDS
#pragma unroll
        for (int r = 0; r < 4; r++)
#pragma unroll
            for (int t = 0; t < TT; t++)
                acc[r][t] = fmaf(x[r], wv[t], acc[r][t]);
    }

    // butterfly reduce each of the 36 partials across lanes
#pragma unroll
    for (int r = 0; r < 4; r++)
#pragma unroll
        for (int t = 0; t < TT; t++)
#pragma unroll
            for (int o = 16; o; o >>= 1)
                acc[r][t] += __shfl_xor_sync(0xffffffffu, acc[r][t], o);

    if (lane < 4) {
        float* o = logits + (size_t)(rowbase + lane) * TT;
#pragma unroll
        for (int t = 0; t < TT; t++) o[t] = acc[lane][t] + g_beff[t];
    }
}

// ---------------------------------------------------------------------------
// Kernel 3: per-(batch,chunk) 9x9 log-semiring composite (linear domain with
// periodic max-renorm). Warp per chunk, lanes 0..8 = matrix column.
// grid (4,64) x 128 thr.
// ---------------------------------------------------------------------------
__global__ __launch_bounds__(128) void crf_chunk_kernel(
    const float* __restrict__ logits, const int* __restrict__ mask,
    const float* __restrict__ trans)
{
    __shared__ float s_em[4][CL * TT];
    __shared__ int   s_mk[4][CL];

    int b = blockIdx.y;
    int w = threadIdx.x >> 5, l = threadIdx.x & 31;
    int c = blockIdx.x * 4 + w;
    int t0 = 1 + c * CL;
    int nst = min(CL, SS - t0);        // 32, except last chunk = 31

    const float* emb = logits + ((size_t)b * SS + t0) * TT;
    for (int i = l; i < nst * TT; i += 32) s_em[w][i] = emb[i];
    const int* mkb = mask + (size_t)b * SS;
    for (int i = l; i < nst; i += 32) s_mk[w][i] = mkb[t0 + i];
    __syncwarp();

    bool act = (l < TT);
    float E[TT];
#pragma unroll
    for (int k = 0; k < TT; k++) E[k] = act ? __expf(trans[k * TT + l]) : 0.f;

    float R[TT], Ms[TT];
#pragma unroll
    for (int i = 0; i < TT; i++) { R[i] = (act && i == l) ? 1.f : 0.f; Ms[i] = 0.f; }

    for (int s = 0; s < nst; s++) {
        if (s_mk[w][s] != 0) {
            float eem = act ? __expf(s_em[w][s * TT + l]) : 0.f;
#pragma unroll
            for (int i = 0; i < TT; i++) {
                float p = R[i];
                float sum = 0.f;
#pragma unroll
                for (int k = 0; k < TT; k++)
                    sum = fmaf(__shfl_sync(0xffffffffu, p, k), E[k], sum);
                R[i] = sum * eem;
            }
        }
        if ((s & 7) == 7) {            // renorm: rows stay in fp32 range
#pragma unroll
            for (int i = 0; i < TT; i++) {
                float m = R[i];
#pragma unroll
                for (int o = 8; o; o >>= 1)
                    m = fmaxf(m, __shfl_xor_sync(0xffffffffu, m, o));
                float r = __fdividef(1.f, m);
                R[i] *= r;
                Ms[i] += __logf(m);
            }
        }
    }
    if (act) {
        float* Pp = g_P + ((size_t)b * NC + c) * 81;
#pragma unroll
        for (int i = 0; i < TT; i++) Pp[i * TT + l] = Ms[i] + __logf(R[i]);
    }
}

// ---------------------------------------------------------------------------
// Kernel 4: per-batch combine. Block of 256 threads per batch.
// Tree of 9x9 log-semiring products (4 levels), + numerator + logz.
// ---------------------------------------------------------------------------
__global__ __launch_bounds__(256) void crf_combine_kernel(
    const float* __restrict__ logits, const int* __restrict__ labels,
    const int* __restrict__ mask, const float* __restrict__ start,
    const float* __restrict__ endt, const float* __restrict__ trans)
{
    __shared__ float sP[NC * 108];     // matrix c at c*108, entry [i][j] at i*12+j
    __shared__ int   s_mk[SS];
    __shared__ int   s_tg[SS];
    __shared__ float s_red[256];
    __shared__ int   s_ridx[256];
    __shared__ float s_alpha[TT];
    __shared__ float s_score;

    int b = blockIdx.x, tid = threadIdx.x;

    const float* Pb = g_P + (size_t)b * NC * 81;
    for (int i = tid; i < NC * 81; i += 256) {
        int c = i / 81, r = i % 81;
        sP[c * 108 + (r / TT) * 12 + r % TT] = Pb[i];
    }
    for (int i = tid; i < SS; i += 256) {
        s_mk[i] = mask[(size_t)b * SS + i];
        s_tg[i] = labels[(size_t)b * SS + i];
    }
    __syncthreads();

    // ---- numerator partial + last-masked-index (each thread: t, t+256) ----
    float contrib = 0.f;
    int ridx = 0;
#pragma unroll
    for (int h = 0; h < 2; h++) {
        int t = tid + h * 256;
        if (t == 0) {
            contrib += start[s_tg[0]] + logits[(size_t)b * SS * TT + s_tg[0]];
        } else if (s_mk[t] > 0) {
            int tp = t - 1;
            while (tp > 0 && s_mk[tp] == 0) tp--;
            contrib += trans[s_tg[tp] * TT + s_tg[t]]
                     + logits[((size_t)b * SS + t) * TT + s_tg[t]];
            ridx = max(ridx, t);
        }
    }
    s_red[tid] = contrib;
    s_ridx[tid] = ridx;
    __syncthreads();
#pragma unroll
    for (int o = 128; o; o >>= 1) {
        if (tid < o) {
            s_red[tid] += s_red[tid + o];
            s_ridx[tid] = max(s_ridx[tid], s_ridx[tid + o]);
        }
        __syncthreads();
    }
    if (tid == 0) s_score = s_red[0] + endt[s_tg[s_ridx[0]]];

    // ---- tree combine: 4 levels; level L: (8>>L) warps, stride 1<<L ----
    int w = tid >> 5, lane = tid & 31;
#pragma unroll
    for (int L = 0; L < 4; L++) {
        __syncthreads();
        int nprod = 8 >> L, stride = 1 << L;
        if (w < nprod && lane < TT) {
            int a = (w * 2) * stride, bb2 = a + stride;
            const float* A = sP + a * 108;
            const float* Bc = sP + bb2 * 108;
            float Bcol[TT];
#pragma unroll
            for (int k = 0; k < TT; k++) Bcol[k] = Bc[k * 12 + lane];
            float C[TT];
#pragma unroll
            for (int i = 0; i < TT; i++) {
                float vmax = -1e30f;
                float vv[TT];
#pragma unroll
                for (int k = 0; k < TT; k++) {
                    vv[k] = A[i * 12 + k] + Bcol[k];
                    vmax = fmaxf(vmax, vv[k]);
                }
                float ssum = 0.f;
#pragma unroll
                for (int k = 0; k < TT; k++) ssum += __expf(vv[k] - vmax);
                C[i] = vmax + __logf(ssum);
            }
            float* Cs = sP + a * 108;
#pragma unroll
            for (int i = 0; i < TT; i++) Cs[i * 12 + lane] = C[i];
        }
    }
    __syncthreads();

    // ---- final: alpha0 (x) P, logz, result ----
    if (w == 0) {
        if (lane < TT)
            s_alpha[lane] = start[lane] + logits[(size_t)b * SS * TT + lane];
        __syncwarp();
        float v = -1e30f;
        if (lane < TT) {
            float vmax = -1e30f, vv[TT];
#pragma unroll
            for (int i = 0; i < TT; i++) {
                vv[i] = s_alpha[i] + sP[i * 12 + lane];
                vmax = fmaxf(vmax, vv[i]);
            }
            float ssum = 0.f;
#pragma unroll
            for (int i = 0; i < TT; i++) ssum += __expf(vv[i] - vmax);
            v = vmax + __logf(ssum) + endt[lane];
        }
        float Mx = v;
#pragma unroll
        for (int o = 16; o; o >>= 1) Mx = fmaxf(Mx, __shfl_xor_sync(0xffffffffu, Mx, o));
        float e = __expf(v - Mx);
#pragma unroll
        for (int o = 16; o; o >>= 1) e += __shfl_xor_sync(0xffffffffu, e, o);
        if (lane == 0) g_res[b] = (Mx + __logf(e)) - s_score;
    }
}

// ---------------------------------------------------------------------------
// Kernel 5: loss = mean(res), fixed-order reduce
// ---------------------------------------------------------------------------
__global__ __launch_bounds__(64) void final_kernel(float* __restrict__ out)
{
    __shared__ float sv[BB];
    int t = threadIdx.x;
    sv[t] = g_res[t];
    __syncthreads();
#pragma unroll
    for (int o = 32; o; o >>= 1) {
        if (t < o) sv[t] += sv[t + o];
        __syncthreads();
    }
    if (t == 0) out[0] = sv[0] * (1.0f / 64.0f);
}

// ---------------------------------------------------------------------------
extern "C" void kernel_launch(void* const* d_in, const int* in_sizes, int n_in,
                              void* d_out, int out_size)
{
    const float* input  = (const float*)d_in[0];
    const int*   labels = (const int*)  d_in[1];
    const int*   mask   = (const int*)  d_in[2];
    const float* W1     = (const float*)d_in[3];
    const float* b1     = (const float*)d_in[4];
    const float* W2     = (const float*)d_in[5];
    const float* b2     = (const float*)d_in[6];
    const float* start  = (const float*)d_in[7];
    const float* endt   = (const float*)d_in[8];
    const float* trans  = (const float*)d_in[9];

    float* out    = (float*)d_out;
    float* logits = out + 1;   // output layout: [loss, logits(B,S,T)]

    weff_kernel<<<DD / 8 + 1, 256>>>(W1, b1, W2, b2);
    gemv_kernel<<<1024, 256>>>(input, logits);
    crf_chunk_kernel<<<dim3(4, BB), 128>>>(logits, mask, trans);
    crf_combine_kernel<<<BB, 256>>>(logits, labels, mask, start, endt, trans);
    final_kernel<<<1, BB>>>(out);
}